// round 1
// baseline (speedup 1.0000x reference)
#include <cuda_runtime.h>
#include <cuda_fp16.h>
#include <cstdint>

// Problem constants
#define BN 8
#define CCH 128      // channels (K of the Gram GEMM)
#define HH 128
#define WW 256
#define NI 65        // disparities 0..64

// Tiling
#define WT 64        // w rows per block
#define KC 32        // channel chunk staged in smem
#define LDA 72       // X1s stride in halves (144 B = 9*16 -> 4-bank rotation, 16B aligned rows)
#define LDB 136      // X2s stride in halves (272 B = 17*16)
#define LDC 130      // Cs stride in floats

__global__ __launch_bounds__(256, 2)
void corr_volume_kernel(const float* __restrict__ x1,
                        const float* __restrict__ x2,
                        float* __restrict__ out)
{
    __shared__ __align__(16) __half X1s[KC * LDA];   //  4608 B
    __shared__ __align__(16) __half X2s[KC * LDB];   //  8704 B
    __shared__ __align__(16) float  Cs[WT * LDC];    // 33280 B  (total 46592 B static)

    const int w0 = blockIdx.x * WT;     // 0,64,128,192
    const int h  = blockIdx.y;
    const int n  = blockIdx.z;

    const int tid  = threadIdx.x;
    const int lane = tid & 31;
    const int wid  = tid >> 5;
    const int wm   = wid >> 1;          // 0..3  (16 w-rows each)
    const int wn   = wid & 1;           // 0..1  (64 w'-cols each)
    const int m0   = wm * 16;

    // 8 n-tiles (8 cols each) x 4 accum regs
    float acc[8][4];
    #pragma unroll
    for (int t = 0; t < 8; t++)
        #pragma unroll
        for (int j = 0; j < 4; j++) acc[t][j] = 0.f;

    const uint32_t x1s_base = (uint32_t)__cvta_generic_to_shared(X1s);
    const uint32_t x2s_base = (uint32_t)__cvta_generic_to_shared(X2s);
    const int r = lane & 7;
    // A fragment addresses (ldmatrix x4 .trans from [k][m] tile):
    //   g0: (k0+r, m0)  g1: (k0+r, m0+8)  g2: (k0+8+r, m0)  g3: (k0+8+r, m0+8)
    const uint32_t addrA0 = x1s_base +
        2u * ((uint32_t)((r + ((lane >> 4) & 1) * 8) * LDA + (m0 + ((lane >> 3) & 1) * 8)));
    // B fragment addresses (ldmatrix x4 .trans from [k][n] tile):
    //   g0: (k0+r, n0)  g1: (k0+8+r, n0)  g2: (k0+r, n0+8)  g3: (k0+8+r, n0+8)
    const uint32_t addrB0 = x2s_base +
        2u * ((uint32_t)((r + ((lane >> 3) & 1) * 8) * LDB + (wn * 64 + ((lane >> 4) & 1) * 8)));

    const size_t cstride = (size_t)HH * WW;
    const float* x1p = x1 + ((size_t)n * CCH * HH + (size_t)h) * WW + w0;
    const float* x2p = x2 + ((size_t)n * CCH * HH + (size_t)h) * WW + (w0 - 64);

    for (int kc = 0; kc < CCH / KC; kc++) {
        if (kc) __syncthreads();   // WAR: prior k-step reads done before refill

        // ---- load X1 chunk: KC x 64 fp32 -> fp16, float4 vectorized (512 float4) ----
        #pragma unroll
        for (int it = 0; it < 2; it++) {
            int idx = tid + it * 256;          // float4 index
            int cr  = idx >> 4;                // 16 float4 per 64-wide row
            int col = (idx & 15) * 4;
            float4 v = *(const float4*)(x1p + (size_t)(kc * KC + cr) * cstride + col);
            __half2* d = (__half2*)&X1s[cr * LDA + col];
            d[0] = __floats2half2_rn(v.x, v.y);
            d[1] = __floats2half2_rn(v.z, v.w);
        }
        // ---- load X2 chunk: KC x 128 (w' in [w0-64, w0+64)), zero-fill w'<0 ----
        #pragma unroll
        for (int it = 0; it < 4; it++) {
            int idx = tid + it * 256;
            int cr  = idx >> 5;                // 32 float4 per 128-wide row
            int col = (idx & 31) * 4;
            float4 v;
            if (w0 - 64 + col >= 0)
                v = *(const float4*)(x2p + (size_t)(kc * KC + cr) * cstride + col);
            else
                v = make_float4(0.f, 0.f, 0.f, 0.f);
            __half2* d = (__half2*)&X2s[cr * LDB + col];
            d[0] = __floats2half2_rn(v.x, v.y);
            d[1] = __floats2half2_rn(v.z, v.w);
        }
        __syncthreads();

        // ---- 2 k-steps of 16 over this chunk ----
        #pragma unroll
        for (int ks = 0; ks < KC / 16; ks++) {
            uint32_t a0, a1, a2, a3;
            uint32_t aaddr = addrA0 + 2u * (uint32_t)(ks * 16 * LDA);
            asm volatile(
                "ldmatrix.sync.aligned.m8n8.x4.trans.shared.b16 {%0,%1,%2,%3}, [%4];\n"
                : "=r"(a0), "=r"(a1), "=r"(a2), "=r"(a3) : "r"(aaddr));
            #pragma unroll
            for (int p = 0; p < 4; p++) {      // 2 n-tiles per ldmatrix
                uint32_t b0, b1, b2, b3;
                uint32_t baddr = addrB0 + 2u * (uint32_t)(ks * 16 * LDB + p * 16);
                asm volatile(
                    "ldmatrix.sync.aligned.m8n8.x4.trans.shared.b16 {%0,%1,%2,%3}, [%4];\n"
                    : "=r"(b0), "=r"(b1), "=r"(b2), "=r"(b3) : "r"(baddr));
                asm volatile(
                    "mma.sync.aligned.m16n8k16.row.col.f32.f16.f16.f32 "
                    "{%0,%1,%2,%3}, {%4,%5,%6,%7}, {%8,%9}, {%0,%1,%2,%3};\n"
                    : "+f"(acc[2*p][0]), "+f"(acc[2*p][1]), "+f"(acc[2*p][2]), "+f"(acc[2*p][3])
                    : "r"(a0), "r"(a1), "r"(a2), "r"(a3), "r"(b0), "r"(b1));
                asm volatile(
                    "mma.sync.aligned.m16n8k16.row.col.f32.f16.f16.f32 "
                    "{%0,%1,%2,%3}, {%4,%5,%6,%7}, {%8,%9}, {%0,%1,%2,%3};\n"
                    : "+f"(acc[2*p+1][0]), "+f"(acc[2*p+1][1]), "+f"(acc[2*p+1][2]), "+f"(acc[2*p+1][3])
                    : "r"(a0), "r"(a1), "r"(a2), "r"(a3), "r"(b2), "r"(b3));
            }
        }
    }

    // ---- stage C (64 w x 128 w') to smem for coalesced de-banding ----
    #pragma unroll
    for (int t = 0; t < 8; t++) {
        int colb = wn * 64 + t * 8 + 2 * (lane & 3);
        int row  = m0 + (lane >> 2);
        Cs[row * LDC + colb]           = acc[t][0];
        Cs[row * LDC + colb + 1]       = acc[t][1];
        Cs[(row + 8) * LDC + colb]     = acc[t][2];
        Cs[(row + 8) * LDC + colb + 1] = acc[t][3];
    }
    __syncthreads();

    // ---- write out[n, i, h, w0+wl] = Cs[wl][wl + 64 - i] / 128 ----
    // diagonal read stride = LDC+1 = 131 floats -> gcd(131,32)=1, conflict-free
    for (int idx = tid; idx < NI * WT; idx += 256) {
        int i  = idx >> 6;
        int wl = idx & 63;
        float v = Cs[wl * LDC + wl + 64 - i] * (1.0f / 128.0f);
        out[(((size_t)n * NI + i) * HH + h) * WW + w0 + wl] = v;
    }
}

extern "C" void kernel_launch(void* const* d_in, const int* in_sizes, int n_in,
                              void* d_out, int out_size)
{
    const float* x1 = (const float*)d_in[0];
    const float* x2 = (const float*)d_in[1];
    float* out = (float*)d_out;
    (void)in_sizes; (void)n_in; (void)out_size;

    dim3 grid(WW / WT, HH, BN);   // (4, 128, 8) = 4096 blocks
    dim3 block(256);
    corr_volume_kernel<<<grid, block>>>(x1, x2, out);
}

// round 2
// speedup vs baseline: 1.1766x; 1.1766x over previous
#include <cuda_runtime.h>
#include <cuda_fp16.h>
#include <cstdint>

// Problem constants
#define BN 8
#define CCH 128      // channels (K of the Gram GEMM)
#define HH 128
#define WW 256
#define NI 65        // disparities 0..64

// Tiling
#define WT 64        // w rows per block
#define KC 32        // channel chunk staged in smem
#define LDA 72       // X1s stride in halves (144 B = 9*16 -> 4-bank rotation)
#define LDB 136      // X2s stride in halves (272 B = 17*16)
#define LDC 130      // Cs stride in floats

#define X1BUF (KC * LDA)   // halves per X1 buffer
#define X2BUF (KC * LDB)   // halves per X2 buffer

__global__ __launch_bounds__(256, 2)
void corr_volume_kernel(const float* __restrict__ x1,
                        const float* __restrict__ x2,
                        float* __restrict__ out)
{
    // X buffers (double) are dead by the epilogue -> overlay Cs on them.
    union SmemU {
        struct {
            __half x1s[2][X1BUF];   // 2 x 4608 B
            __half x2s[2][X2BUF];   // 2 x 8704 B
        } s;                        // 26624 B
        float cs[WT * LDC];         // 33280 B
    };
    __shared__ __align__(16) SmemU sm;

    const int w0 = blockIdx.x * WT;     // 0,64,128,192
    const int h  = blockIdx.y;
    const int n  = blockIdx.z;

    const int tid  = threadIdx.x;
    const int lane = tid & 31;
    const int wid  = tid >> 5;
    const int wm   = wid >> 1;          // 0..3  (16 w-rows each)
    const int wn   = wid & 1;           // 0..1  (64 w'-cols each)
    const int m0   = wm * 16;

    float acc[8][4];
    #pragma unroll
    for (int t = 0; t < 8; t++)
        #pragma unroll
        for (int j = 0; j < 4; j++) acc[t][j] = 0.f;

    const uint32_t x1s_base = (uint32_t)__cvta_generic_to_shared(sm.s.x1s[0]);
    const uint32_t x2s_base = (uint32_t)__cvta_generic_to_shared(sm.s.x2s[0]);
    const int r = lane & 7;
    // A frag (ldmatrix x4 .trans from [k][m]): g0:(k0+r,m0) g1:(k0+r,m0+8) g2:(k0+8+r,m0) g3:(k0+8+r,m0+8)
    const uint32_t addrA0 = x1s_base +
        2u * ((uint32_t)((r + ((lane >> 4) & 1) * 8) * LDA + (m0 + ((lane >> 3) & 1) * 8)));
    // B frag (ldmatrix x4 .trans from [k][n]): g0:(k0+r,n0) g1:(k0+8+r,n0) g2:(k0+r,n0+8) g3:(k0+8+r,n0+8)
    const uint32_t addrB0 = x2s_base +
        2u * ((uint32_t)((r + ((lane >> 3) & 1) * 8) * LDB + (wn * 64 + ((lane >> 4) & 1) * 8)));

    const size_t cstride = (size_t)HH * WW;
    const float* x1p = x1 + ((size_t)n * CCH * HH + (size_t)h) * WW + w0;
    const float* x2p = x2 + ((size_t)n * CCH * HH + (size_t)h) * WW + (w0 - 64);

    // per-thread load coordinates (fixed across chunks)
    const int cr1a = tid >> 4;            // X1: row of 1st float4
    const int co1  = (tid & 15) * 4;      // X1: col
    const int cr2a = tid >> 5;            // X2: row of 1st float4
    const int co2  = (tid & 31) * 4;      // X2: col
    const bool x2ok = (w0 - 64 + co2) >= 0;

    float4 p1[2], p2[4];

    // ---- register prefetch of one chunk ----
    auto load_chunk = [&](int kc) {
        #pragma unroll
        for (int it = 0; it < 2; it++)
            p1[it] = *(const float4*)(x1p + (size_t)(kc * KC + cr1a + it * 16) * cstride + co1);
        #pragma unroll
        for (int it = 0; it < 4; it++) {
            if (x2ok)
                p2[it] = *(const float4*)(x2p + (size_t)(kc * KC + cr2a + it * 8) * cstride + co2);
            else
                p2[it] = make_float4(0.f, 0.f, 0.f, 0.f);
        }
    };
    // ---- convert + store prefetched chunk into buffer `buf` ----
    auto store_chunk = [&](int buf) {
        #pragma unroll
        for (int it = 0; it < 2; it++) {
            __half2* d = (__half2*)&sm.s.x1s[buf][(cr1a + it * 16) * LDA + co1];
            d[0] = __floats2half2_rn(p1[it].x, p1[it].y);
            d[1] = __floats2half2_rn(p1[it].z, p1[it].w);
        }
        #pragma unroll
        for (int it = 0; it < 4; it++) {
            __half2* d = (__half2*)&sm.s.x2s[buf][(cr2a + it * 8) * LDB + co2];
            d[0] = __floats2half2_rn(p2[it].x, p2[it].y);
            d[1] = __floats2half2_rn(p2[it].z, p2[it].w);
        }
    };

    // prologue: fill buffer 0
    load_chunk(0);
    store_chunk(0);
    __syncthreads();

    for (int kc = 0; kc < CCH / KC; kc++) {
        const int cur = kc & 1;
        if (kc < CCH / KC - 1)
            load_chunk(kc + 1);                 // LDGs in flight under the MMA phase

        const uint32_t offA = (uint32_t)(cur * X1BUF * 2);
        const uint32_t offB = (uint32_t)(cur * X2BUF * 2);

        #pragma unroll
        for (int ks = 0; ks < KC / 16; ks++) {
            uint32_t a0, a1, a2, a3;
            uint32_t aaddr = addrA0 + offA + 2u * (uint32_t)(ks * 16 * LDA);
            asm volatile(
                "ldmatrix.sync.aligned.m8n8.x4.trans.shared.b16 {%0,%1,%2,%3}, [%4];\n"
                : "=r"(a0), "=r"(a1), "=r"(a2), "=r"(a3) : "r"(aaddr));
            #pragma unroll
            for (int p = 0; p < 4; p++) {
                uint32_t b0, b1, b2, b3;
                uint32_t baddr = addrB0 + offB + 2u * (uint32_t)(ks * 16 * LDB + p * 16);
                asm volatile(
                    "ldmatrix.sync.aligned.m8n8.x4.trans.shared.b16 {%0,%1,%2,%3}, [%4];\n"
                    : "=r"(b0), "=r"(b1), "=r"(b2), "=r"(b3) : "r"(baddr));
                asm volatile(
                    "mma.sync.aligned.m16n8k16.row.col.f32.f16.f16.f32 "
                    "{%0,%1,%2,%3}, {%4,%5,%6,%7}, {%8,%9}, {%0,%1,%2,%3};\n"
                    : "+f"(acc[2*p][0]), "+f"(acc[2*p][1]), "+f"(acc[2*p][2]), "+f"(acc[2*p][3])
                    : "r"(a0), "r"(a1), "r"(a2), "r"(a3), "r"(b0), "r"(b1));
                asm volatile(
                    "mma.sync.aligned.m16n8k16.row.col.f32.f16.f16.f32 "
                    "{%0,%1,%2,%3}, {%4,%5,%6,%7}, {%8,%9}, {%0,%1,%2,%3};\n"
                    : "+f"(acc[2*p+1][0]), "+f"(acc[2*p+1][1]), "+f"(acc[2*p+1][2]), "+f"(acc[2*p+1][3])
                    : "r"(a0), "r"(a1), "r"(a2), "r"(a3), "r"(b2), "r"(b3));
            }
        }

        if (kc < CCH / KC - 1)
            store_chunk((kc + 1) & 1);          // write the *other* buffer (safe: its readers
                                                // finished last iter, fenced by last sync)
        __syncthreads();                        // also fences Cs overlay after last iter
    }

    // ---- stage C (64 w x 128 w') into Cs for coalesced de-banding ----
    #pragma unroll
    for (int t = 0; t < 8; t++) {
        int colb = wn * 64 + t * 8 + 2 * (lane & 3);
        int row  = m0 + (lane >> 2);
        sm.cs[row * LDC + colb]           = acc[t][0];
        sm.cs[row * LDC + colb + 1]       = acc[t][1];
        sm.cs[(row + 8) * LDC + colb]     = acc[t][2];
        sm.cs[(row + 8) * LDC + colb + 1] = acc[t][3];
    }
    __syncthreads();

    // ---- out[n, i, h, w0+wl] = Cs[wl][wl + 64 - i] / 128 ----
    // diagonal read stride = LDC+1 = 131 floats, gcd(131,32)=1 -> conflict-free
    for (int idx = tid; idx < NI * WT; idx += 256) {
        int i  = idx >> 6;
        int wl = idx & 63;
        float v = sm.cs[wl * LDC + wl + 64 - i] * (1.0f / 128.0f);
        out[(((size_t)n * NI + i) * HH + h) * WW + w0 + wl] = v;
    }
}

extern "C" void kernel_launch(void* const* d_in, const int* in_sizes, int n_in,
                              void* d_out, int out_size)
{
    const float* x1 = (const float*)d_in[0];
    const float* x2 = (const float*)d_in[1];
    float* out = (float*)d_out;
    (void)in_sizes; (void)n_in; (void)out_size;

    dim3 grid(WW / WT, HH, BN);   // (4, 128, 8) = 4096 blocks
    dim3 block(256);
    corr_volume_kernel<<<grid, block>>>(x1, x2, out);
}

// round 3
// speedup vs baseline: 1.3070x; 1.1109x over previous
#include <cuda_runtime.h>
#include <cuda_fp16.h>
#include <cstdint>

// Problem constants
#define BN 8
#define CCH 128      // channels (K of the Gram GEMM)
#define HH 128
#define WW 256
#define NI 65        // disparities 0..64

// Tiling
#define WT 64        // w rows per block
#define KC 32        // channel chunk staged in smem
#define LDA 72       // X1s stride in halves (144 B = 9*16 -> 4-bank rotation)
#define LDB 136      // X2s stride in halves (272 B = 17*16)
#define LDC 130      // Cs stride in floats

#define X1BUF (KC * LDA)
#define X2BUF (KC * LDB)

__global__ __launch_bounds__(256, 3)
void corr_volume_kernel(const float* __restrict__ x1,
                        const float* __restrict__ x2,
                        float* __restrict__ out)
{
    union SmemU {
        struct {
            __half x1s[2][X1BUF];   // 2 x 4608 B
            __half x2s[2][X2BUF];   // 2 x 8704 B
        } s;                        // 26624 B
        float cs[WT * LDC];         // 33280 B
    };
    __shared__ __align__(16) SmemU sm;

    const int w0 = blockIdx.x * WT;
    const int h  = blockIdx.y;
    const int n  = blockIdx.z;

    const int tid  = threadIdx.x;
    const int lane = tid & 31;
    const int wid  = tid >> 5;
    // 2x4 warp grid: 32-row x 32-col warp tiles
    const int wm   = wid >> 2;          // 0..1
    const int wn   = wid & 3;           // 0..3
    const int m0   = wm * 32;
    const int n0   = wn * 32;

    // acc[mt][nt][4]: mt in {0,1} (m16 tiles), nt in {0..3} (n8 tiles)
    float acc[2][4][4];
    #pragma unroll
    for (int a = 0; a < 2; a++)
        #pragma unroll
        for (int t = 0; t < 4; t++)
            #pragma unroll
            for (int j = 0; j < 4; j++) acc[a][t][j] = 0.f;

    const uint32_t x1s_base = (uint32_t)__cvta_generic_to_shared(sm.s.x1s[0]);
    const uint32_t x2s_base = (uint32_t)__cvta_generic_to_shared(sm.s.x2s[0]);
    const int r = lane & 7;
    // A frag (ldmatrix x4 .trans from [k][m] tile)
    const uint32_t addrA0 = x1s_base +
        2u * ((uint32_t)((r + ((lane >> 4) & 1) * 8) * LDA + (m0 + ((lane >> 3) & 1) * 8)));
    const uint32_t addrA1 = addrA0 + 2u * 16u;   // +16 m-cols
    // B frag (ldmatrix x4 .trans from [k][n] tile): covers 16 n-cols -> 2 n8 operands
    const uint32_t addrB0 = x2s_base +
        2u * ((uint32_t)((r + ((lane >> 3) & 1) * 8) * LDB + (n0 + ((lane >> 4) & 1) * 8)));

    const size_t cstride = (size_t)HH * WW;
    const float* x1p = x1 + ((size_t)n * CCH * HH + (size_t)h) * WW + w0;
    const float* x2p = x2 + ((size_t)n * CCH * HH + (size_t)h) * WW + (w0 - 64);

    const int cr1a = tid >> 4;            // X1 row of 1st float4
    const int co1  = (tid & 15) * 4;
    const int cr2a = tid >> 5;            // X2 row of 1st float4
    const int co2  = (tid & 31) * 4;
    const bool x2ok = (w0 - 64 + co2) >= 0;

    float4 p1[2], p2[4];

    auto load_chunk = [&](int kc) {
        #pragma unroll
        for (int it = 0; it < 2; it++)
            p1[it] = *(const float4*)(x1p + (size_t)(kc * KC + cr1a + it * 16) * cstride + co1);
        #pragma unroll
        for (int it = 0; it < 4; it++) {
            if (x2ok)
                p2[it] = *(const float4*)(x2p + (size_t)(kc * KC + cr2a + it * 8) * cstride + co2);
            else
                p2[it] = make_float4(0.f, 0.f, 0.f, 0.f);
        }
    };
    auto store_chunk = [&](int buf) {
        #pragma unroll
        for (int it = 0; it < 2; it++) {
            __half2* d = (__half2*)&sm.s.x1s[buf][(cr1a + it * 16) * LDA + co1];
            d[0] = __floats2half2_rn(p1[it].x, p1[it].y);
            d[1] = __floats2half2_rn(p1[it].z, p1[it].w);
        }
        #pragma unroll
        for (int it = 0; it < 4; it++) {
            __half2* d = (__half2*)&sm.s.x2s[buf][(cr2a + it * 8) * LDB + co2];
            d[0] = __floats2half2_rn(p2[it].x, p2[it].y);
            d[1] = __floats2half2_rn(p2[it].z, p2[it].w);
        }
    };

    load_chunk(0);
    store_chunk(0);
    __syncthreads();

    for (int kc = 0; kc < CCH / KC; kc++) {
        const int cur = kc & 1;
        if (kc < CCH / KC - 1)
            load_chunk(kc + 1);

        const uint32_t offA = (uint32_t)(cur * X1BUF * 2);
        const uint32_t offB = (uint32_t)(cur * X2BUF * 2);

        #pragma unroll
        for (int ks = 0; ks < KC / 16; ks++) {
            uint32_t a0[4], a1[4];
            {
                uint32_t aaddr = addrA0 + offA + 2u * (uint32_t)(ks * 16 * LDA);
                asm volatile(
                    "ldmatrix.sync.aligned.m8n8.x4.trans.shared.b16 {%0,%1,%2,%3}, [%4];\n"
                    : "=r"(a0[0]), "=r"(a0[1]), "=r"(a0[2]), "=r"(a0[3]) : "r"(aaddr));
                aaddr = addrA1 + offA + 2u * (uint32_t)(ks * 16 * LDA);
                asm volatile(
                    "ldmatrix.sync.aligned.m8n8.x4.trans.shared.b16 {%0,%1,%2,%3}, [%4];\n"
                    : "=r"(a1[0]), "=r"(a1[1]), "=r"(a1[2]), "=r"(a1[3]) : "r"(aaddr));
            }
            #pragma unroll
            for (int p = 0; p < 2; p++) {      // 2 B ldmatrix, each 2 n8 operands
                uint32_t b0, b1, b2, b3;
                uint32_t baddr = addrB0 + offB + 2u * (uint32_t)(ks * 16 * LDB + p * 16);
                asm volatile(
                    "ldmatrix.sync.aligned.m8n8.x4.trans.shared.b16 {%0,%1,%2,%3}, [%4];\n"
                    : "=r"(b0), "=r"(b1), "=r"(b2), "=r"(b3) : "r"(baddr));
                asm volatile(
                    "mma.sync.aligned.m16n8k16.row.col.f32.f16.f16.f32 "
                    "{%0,%1,%2,%3}, {%4,%5,%6,%7}, {%8,%9}, {%0,%1,%2,%3};\n"
                    : "+f"(acc[0][2*p][0]), "+f"(acc[0][2*p][1]), "+f"(acc[0][2*p][2]), "+f"(acc[0][2*p][3])
                    : "r"(a0[0]), "r"(a0[1]), "r"(a0[2]), "r"(a0[3]), "r"(b0), "r"(b1));
                asm volatile(
                    "mma.sync.aligned.m16n8k16.row.col.f32.f16.f16.f32 "
                    "{%0,%1,%2,%3}, {%4,%5,%6,%7}, {%8,%9}, {%0,%1,%2,%3};\n"
                    : "+f"(acc[0][2*p+1][0]), "+f"(acc[0][2*p+1][1]), "+f"(acc[0][2*p+1][2]), "+f"(acc[0][2*p+1][3])
                    : "r"(a0[0]), "r"(a0[1]), "r"(a0[2]), "r"(a0[3]), "r"(b2), "r"(b3));
                asm volatile(
                    "mma.sync.aligned.m16n8k16.row.col.f32.f16.f16.f32 "
                    "{%0,%1,%2,%3}, {%4,%5,%6,%7}, {%8,%9}, {%0,%1,%2,%3};\n"
                    : "+f"(acc[1][2*p][0]), "+f"(acc[1][2*p][1]), "+f"(acc[1][2*p][2]), "+f"(acc[1][2*p][3])
                    : "r"(a1[0]), "r"(a1[1]), "r"(a1[2]), "r"(a1[3]), "r"(b0), "r"(b1));
                asm volatile(
                    "mma.sync.aligned.m16n8k16.row.col.f32.f16.f16.f32 "
                    "{%0,%1,%2,%3}, {%4,%5,%6,%7}, {%8,%9}, {%0,%1,%2,%3};\n"
                    : "+f"(acc[1][2*p+1][0]), "+f"(acc[1][2*p+1][1]), "+f"(acc[1][2*p+1][2]), "+f"(acc[1][2*p+1][3])
                    : "r"(a1[0]), "r"(a1[1]), "r"(a1[2]), "r"(a1[3]), "r"(b2), "r"(b3));
            }
        }

        if (kc < CCH / KC - 1)
            store_chunk((kc + 1) & 1);
        __syncthreads();
    }

    // ---- stage C (64 w x 128 w') into Cs ----
    #pragma unroll
    for (int mt = 0; mt < 2; mt++) {
        #pragma unroll
        for (int nt = 0; nt < 4; nt++) {
            int row  = m0 + mt * 16 + (lane >> 2);
            int colb = n0 + nt * 8 + 2 * (lane & 3);
            sm.cs[row * LDC + colb]           = acc[mt][nt][0];
            sm.cs[row * LDC + colb + 1]       = acc[mt][nt][1];
            sm.cs[(row + 8) * LDC + colb]     = acc[mt][nt][2];
            sm.cs[(row + 8) * LDC + colb + 1] = acc[mt][nt][3];
        }
    }
    __syncthreads();

    // ---- out[n, i, h, w0+wl] = Cs[wl][wl + 64 - i] / 128 ----
    for (int idx = tid; idx < NI * WT; idx += 256) {
        int i  = idx >> 6;
        int wl = idx & 63;
        float v = sm.cs[wl * LDC + wl + 64 - i] * (1.0f / 128.0f);
        out[(((size_t)n * NI + i) * HH + h) * WW + w0 + wl] = v;
    }
}

extern "C" void kernel_launch(void* const* d_in, const int* in_sizes, int n_in,
                              void* d_out, int out_size)
{
    const float* x1 = (const float*)d_in[0];
    const float* x2 = (const float*)d_in[1];
    float* out = (float*)d_out;
    (void)in_sizes; (void)n_in; (void)out_size;

    dim3 grid(WW / WT, HH, BN);   // (4, 128, 8)
    dim3 block(256);
    corr_volume_kernel<<<grid, block>>>(x1, x2, out);
}

// round 4
// speedup vs baseline: 1.4025x; 1.0730x over previous
#include <cuda_runtime.h>
#include <cuda_fp16.h>
#include <cstdint>

// Problem constants
#define BN 8
#define CCH 128
#define HH 128
#define WW 256
#define NI 65

// Tiling
#define WT 64
#define KC 32
#define LDA 72      // X1s stride in halves
#define LDB 136     // X2s stride in halves
#define LDC 130     // Cs stride in floats

#define X1BUF (KC * LDA)
#define X2BUF (KC * LDB)

__global__ __launch_bounds__(256, 4)
void corr_volume_kernel(const float* __restrict__ x1,
                        const float* __restrict__ x2,
                        float* __restrict__ out)
{
    union SmemU {
        struct {
            __half x1s[2][X1BUF];   // 2 x 4608 B
            __half x2s[2][X2BUF];   // 2 x 8704 B
        } s;                        // 26624 B
        float cs[WT * LDC];         // 33280 B
    };
    __shared__ __align__(16) SmemU sm;

    const int w0 = blockIdx.x * WT;
    const int h  = blockIdx.y;
    const int n  = blockIdx.z;

    const int tid  = threadIdx.x;
    const int lane = tid & 31;
    const int wid  = tid >> 5;
    // 4x2 warp grid, BANDED: warp (wm, wn) computes m-tile rows [m0, m0+16)
    // and 5 n8-tiles of the needed band j in [m0, m0+80), offset wn*40.
    const int wm   = wid >> 1;          // 0..3
    const int wn   = wid & 1;           // 0..1
    const int m0   = wm * 16;
    const int nst  = m0 + wn * 40;      // first band column for this warp

    // 5 n8-tiles x 4 accum regs
    float acc[5][4];
    #pragma unroll
    for (int t = 0; t < 5; t++)
        #pragma unroll
        for (int j = 0; j < 4; j++) acc[t][j] = 0.f;

    const uint32_t x1s_base = (uint32_t)__cvta_generic_to_shared(sm.s.x1s[0]);
    const uint32_t x2s_base = (uint32_t)__cvta_generic_to_shared(sm.s.x2s[0]);
    const int r = lane & 7;
    // A frag (x4 .trans from [k][m]): g0:(k0+r,m0) g1:(k0+r,m0+8) g2:(k0+8+r,m0) g3:(k0+8+r,m0+8)
    const uint32_t addrA0 = x1s_base +
        2u * ((uint32_t)((r + ((lane >> 4) & 1) * 8) * LDA + (m0 + ((lane >> 3) & 1) * 8)));
    // B frag (x4 .trans from [k][n]): g0:(k0+r,n0) g1:(k0+8+r,n0) g2:(k0+r,n0+8) g3:(k0+8+r,n0+8)
    // (x2 variant uses lanes 0..15 -> g0:(k0+r,n0) g1:(k0+8+r,n0), same formula)
    const uint32_t addrB0 = x2s_base +
        2u * ((uint32_t)((r + ((lane >> 3) & 1) * 8) * LDB + (nst + ((lane >> 4) & 1) * 8)));

    const size_t cstride = (size_t)HH * WW;
    const float* x1p = x1 + ((size_t)n * CCH * HH + (size_t)h) * WW + w0;
    const float* x2p = x2 + ((size_t)n * CCH * HH + (size_t)h) * WW + (w0 - 64);

    const int cr1a = tid >> 4;
    const int co1  = (tid & 15) * 4;
    const int cr2a = tid >> 5;
    const int co2  = (tid & 31) * 4;
    const bool x2ok = (w0 - 64 + co2) >= 0;

    float4 p1[2], p2[4];

    auto load_chunk = [&](int kc) {
        #pragma unroll
        for (int it = 0; it < 2; it++)
            p1[it] = *(const float4*)(x1p + (size_t)(kc * KC + cr1a + it * 16) * cstride + co1);
        #pragma unroll
        for (int it = 0; it < 4; it++) {
            if (x2ok)
                p2[it] = *(const float4*)(x2p + (size_t)(kc * KC + cr2a + it * 8) * cstride + co2);
            else
                p2[it] = make_float4(0.f, 0.f, 0.f, 0.f);
        }
    };
    auto store_chunk = [&](int buf) {
        #pragma unroll
        for (int it = 0; it < 2; it++) {
            __half2* d = (__half2*)&sm.s.x1s[buf][(cr1a + it * 16) * LDA + co1];
            d[0] = __floats2half2_rn(p1[it].x, p1[it].y);
            d[1] = __floats2half2_rn(p1[it].z, p1[it].w);
        }
        #pragma unroll
        for (int it = 0; it < 4; it++) {
            __half2* d = (__half2*)&sm.s.x2s[buf][(cr2a + it * 8) * LDB + co2];
            d[0] = __floats2half2_rn(p2[it].x, p2[it].y);
            d[1] = __floats2half2_rn(p2[it].z, p2[it].w);
        }
    };

    load_chunk(0);
    store_chunk(0);
    __syncthreads();

    for (int kc = 0; kc < CCH / KC; kc++) {
        const int cur = kc & 1;
        if (kc < CCH / KC - 1)
            load_chunk(kc + 1);

        const uint32_t offA = (uint32_t)(cur * X1BUF * 2);
        const uint32_t offB = (uint32_t)(cur * X2BUF * 2);

        #pragma unroll
        for (int ks = 0; ks < KC / 16; ks++) {
            uint32_t a[4];
            {
                uint32_t aaddr = addrA0 + offA + 2u * (uint32_t)(ks * 16 * LDA);
                asm volatile(
                    "ldmatrix.sync.aligned.m8n8.x4.trans.shared.b16 {%0,%1,%2,%3}, [%4];\n"
                    : "=r"(a[0]), "=r"(a[1]), "=r"(a[2]), "=r"(a[3]) : "r"(aaddr));
            }
            // two x4 B loads (tiles 0..3)
            #pragma unroll
            for (int p = 0; p < 2; p++) {
                uint32_t b0, b1, b2, b3;
                uint32_t baddr = addrB0 + offB + 2u * (uint32_t)(ks * 16 * LDB + p * 16);
                asm volatile(
                    "ldmatrix.sync.aligned.m8n8.x4.trans.shared.b16 {%0,%1,%2,%3}, [%4];\n"
                    : "=r"(b0), "=r"(b1), "=r"(b2), "=r"(b3) : "r"(baddr));
                asm volatile(
                    "mma.sync.aligned.m16n8k16.row.col.f32.f16.f16.f32 "
                    "{%0,%1,%2,%3}, {%4,%5,%6,%7}, {%8,%9}, {%0,%1,%2,%3};\n"
                    : "+f"(acc[2*p][0]), "+f"(acc[2*p][1]), "+f"(acc[2*p][2]), "+f"(acc[2*p][3])
                    : "r"(a[0]), "r"(a[1]), "r"(a[2]), "r"(a[3]), "r"(b0), "r"(b1));
                asm volatile(
                    "mma.sync.aligned.m16n8k16.row.col.f32.f16.f16.f32 "
                    "{%0,%1,%2,%3}, {%4,%5,%6,%7}, {%8,%9}, {%0,%1,%2,%3};\n"
                    : "+f"(acc[2*p+1][0]), "+f"(acc[2*p+1][1]), "+f"(acc[2*p+1][2]), "+f"(acc[2*p+1][3])
                    : "r"(a[0]), "r"(a[1]), "r"(a[2]), "r"(a[3]), "r"(b2), "r"(b3));
            }
            // one x2 B load (tile 4)
            {
                uint32_t b0, b1;
                uint32_t baddr = addrB0 + offB + 2u * (uint32_t)(ks * 16 * LDB + 32);
                asm volatile(
                    "ldmatrix.sync.aligned.m8n8.x2.trans.shared.b16 {%0,%1}, [%2];\n"
                    : "=r"(b0), "=r"(b1) : "r"(baddr));
                asm volatile(
                    "mma.sync.aligned.m16n8k16.row.col.f32.f16.f16.f32 "
                    "{%0,%1,%2,%3}, {%4,%5,%6,%7}, {%8,%9}, {%0,%1,%2,%3};\n"
                    : "+f"(acc[4][0]), "+f"(acc[4][1]), "+f"(acc[4][2]), "+f"(acc[4][3])
                    : "r"(a[0]), "r"(a[1]), "r"(a[2]), "r"(a[3]), "r"(b0), "r"(b1));
            }
        }

        if (kc < CCH / KC - 1)
            store_chunk((kc + 1) & 1);
        __syncthreads();
    }

    // ---- stage the band into Cs (only band entries are later read) ----
    #pragma unroll
    for (int t = 0; t < 5; t++) {
        int row  = m0 + (lane >> 2);
        int colb = nst + t * 8 + 2 * (lane & 3);
        sm.cs[row * LDC + colb]           = acc[t][0];
        sm.cs[row * LDC + colb + 1]       = acc[t][1];
        sm.cs[(row + 8) * LDC + colb]     = acc[t][2];
        sm.cs[(row + 8) * LDC + colb + 1] = acc[t][3];
    }
    __syncthreads();

    // ---- out[n, i, h, w0+wl] = Cs[wl][wl + 64 - i] / 128 ----
    for (int idx = tid; idx < NI * WT; idx += 256) {
        int i  = idx >> 6;
        int wl = idx & 63;
        float v = sm.cs[wl * LDC + wl + 64 - i] * (1.0f / 128.0f);
        out[(((size_t)n * NI + i) * HH + h) * WW + w0 + wl] = v;
    }
}

extern "C" void kernel_launch(void* const* d_in, const int* in_sizes, int n_in,
                              void* d_out, int out_size)
{
    const float* x1 = (const float*)d_in[0];
    const float* x2 = (const float*)d_in[1];
    float* out = (float*)d_out;
    (void)in_sizes; (void)n_in; (void)out_size;

    dim3 grid(WW / WT, HH, BN);   // (4, 128, 8)
    dim3 block(256);
    corr_volume_kernel<<<grid, block>>>(x1, x2, out);
}

// round 6
// speedup vs baseline: 1.5819x; 1.1279x over previous
#include <cuda_runtime.h>
#include <cuda_fp16.h>
#include <cstdint>

// Problem constants
#define BN 8
#define CCH 128
#define HH 128
#define WW 256
#define NI 65

// Tiling
#define WT 64
#define KC 32
#define LDA 72      // X1s stride in halves
#define LDB 136     // X2s stride in halves
#define LDJ 66      // cs2 stride in floats (cs2[j][row], j in [0,64], row in [0,63])

#define X1BUF (KC * LDA)
#define X2BUF (KC * LDB)

#define GRIDX 592           // 148 SMs x 4 CTAs, all resident (persistent)
#define NTILES (BN * HH * (WW / WT))   // 4096

__global__ __launch_bounds__(256, 4)
void corr_volume_kernel(const float* __restrict__ x1,
                        const float* __restrict__ x2,
                        float* __restrict__ out)
{
    __shared__ __align__(16) __half X1s[2][X1BUF];   // 2 x 4608 B
    __shared__ __align__(16) __half X2s[2][X2BUF];   // 2 x 8704 B
    __shared__ __align__(16) float  cs2[NI * LDJ];   // 17160 B   (total ~43.8 KB)

    const int tid  = threadIdx.x;
    const int lane = tid & 31;
    const int wid  = tid >> 5;
    // 4x2 banded warp grid: warp (wm, wn) -> rows [m0, m0+16), band cols [nst, nst+40)
    const int wm   = wid >> 1;
    const int wn   = wid & 1;
    const int m0   = wm * 16;
    const int nst  = m0 + wn * 40;

    const uint32_t x1s_base = (uint32_t)__cvta_generic_to_shared(X1s);
    const uint32_t x2s_base = (uint32_t)__cvta_generic_to_shared(X2s);
    const int r = lane & 7;
    const uint32_t addrA0 = x1s_base +
        2u * ((uint32_t)((r + ((lane >> 4) & 1) * 8) * LDA + (m0 + ((lane >> 3) & 1) * 8)));
    const uint32_t addrB0 = x2s_base +
        2u * ((uint32_t)((r + ((lane >> 3) & 1) * 8) * LDB + (nst + ((lane >> 4) & 1) * 8)));

    const size_t cstride = (size_t)HH * WW;

    // per-thread load coordinates (fixed)
    const int cr1a = tid >> 4;            // X1 row of 1st float4
    const int co1  = (tid & 15) * 4;
    const int cr2a = tid >> 5;            // X2 row of 1st float4
    const int co2  = (tid & 31) * 4;

    float acc[5][4];
    float4 p1[2], p2[4];

    // tile decode: t -> (bx, h, n); bx = t&3, h = (t>>2)&127, n = t>>9
    auto tile_x1p = [&](int t) -> const float* {
        int bx = t & 3, h = (t >> 2) & (HH - 1), n = t >> 9;
        return x1 + ((size_t)n * CCH * HH + (size_t)h) * WW + bx * WT;
    };
    auto tile_x2p = [&](int t) -> const float* {
        int bx = t & 3, h = (t >> 2) & (HH - 1), n = t >> 9;
        return x2 + ((size_t)n * CCH * HH + (size_t)h) * WW + (bx * WT - 64);
    };

    auto load_chunk = [&](const float* x1p, const float* x2p, bool ok, int kc) {
        #pragma unroll
        for (int it = 0; it < 2; it++)
            p1[it] = *(const float4*)(x1p + (size_t)(kc * KC + cr1a + it * 16) * cstride + co1);
        #pragma unroll
        for (int it = 0; it < 4; it++) {
            if (ok)
                p2[it] = *(const float4*)(x2p + (size_t)(kc * KC + cr2a + it * 8) * cstride + co2);
            else
                p2[it] = make_float4(0.f, 0.f, 0.f, 0.f);
        }
    };
    auto store_chunk = [&](int buf) {
        #pragma unroll
        for (int it = 0; it < 2; it++) {
            __half2* d = (__half2*)&X1s[buf][(cr1a + it * 16) * LDA + co1];
            d[0] = __floats2half2_rn(p1[it].x, p1[it].y);
            d[1] = __floats2half2_rn(p1[it].z, p1[it].w);
        }
        #pragma unroll
        for (int it = 0; it < 4; it++) {
            __half2* d = (__half2*)&X2s[buf][(cr2a + it * 8) * LDB + co2];
            d[0] = __floats2half2_rn(p2[it].x, p2[it].y);
            d[1] = __floats2half2_rn(p2[it].z, p2[it].w);
        }
    };

    int t = blockIdx.x;
    if (t >= NTILES) return;

    const float* x1p = tile_x1p(t);
    const float* x2p = tile_x2p(t);
    bool ok = ((t & 3) != 0) || (co2 >= 64);   // w0-64+co2 >= 0

    // prologue: chunk 0 of first tile
    load_chunk(x1p, x2p, ok, 0);
    store_chunk(0);
    __syncthreads();

    while (true) {
        const int tn = t + GRIDX;
        const bool has_next = (tn < NTILES);
        const float* x1pN = has_next ? tile_x1p(tn) : x1p;
        const float* x2pN = has_next ? tile_x2p(tn) : x2p;
        const bool okN = has_next ? (((tn & 3) != 0) || (co2 >= 64)) : false;

        #pragma unroll
        for (int i5 = 0; i5 < 5; i5++)
            #pragma unroll
            for (int j = 0; j < 4; j++) acc[i5][j] = 0.f;

        for (int kc = 0; kc < CCH / KC; kc++) {
            const int cur = kc & 1;
            const bool pf = (kc < CCH / KC - 1);
            if (pf)
                load_chunk(x1p, x2p, ok, kc + 1);
            else if (has_next)
                load_chunk(x1pN, x2pN, okN, 0);

            const uint32_t offA = (uint32_t)(cur * X1BUF * 2);
            const uint32_t offB = (uint32_t)(cur * X2BUF * 2);

            #pragma unroll
            for (int ks = 0; ks < KC / 16; ks++) {
                uint32_t a[4];
                {
                    uint32_t aaddr = addrA0 + offA + 2u * (uint32_t)(ks * 16 * LDA);
                    asm volatile(
                        "ldmatrix.sync.aligned.m8n8.x4.trans.shared.b16 {%0,%1,%2,%3}, [%4];\n"
                        : "=r"(a[0]), "=r"(a[1]), "=r"(a[2]), "=r"(a[3]) : "r"(aaddr));
                }
                #pragma unroll
                for (int p = 0; p < 2; p++) {
                    uint32_t b0, b1, b2, b3;
                    uint32_t baddr = addrB0 + offB + 2u * (uint32_t)(ks * 16 * LDB + p * 16);
                    asm volatile(
                        "ldmatrix.sync.aligned.m8n8.x4.trans.shared.b16 {%0,%1,%2,%3}, [%4];\n"
                        : "=r"(b0), "=r"(b1), "=r"(b2), "=r"(b3) : "r"(baddr));
                    asm volatile(
                        "mma.sync.aligned.m16n8k16.row.col.f32.f16.f16.f32 "
                        "{%0,%1,%2,%3}, {%4,%5,%6,%7}, {%8,%9}, {%0,%1,%2,%3};\n"
                        : "+f"(acc[2*p][0]), "+f"(acc[2*p][1]), "+f"(acc[2*p][2]), "+f"(acc[2*p][3])
                        : "r"(a[0]), "r"(a[1]), "r"(a[2]), "r"(a[3]), "r"(b0), "r"(b1));
                    asm volatile(
                        "mma.sync.aligned.m16n8k16.row.col.f32.f16.f16.f32 "
                        "{%0,%1,%2,%3}, {%4,%5,%6,%7}, {%8,%9}, {%0,%1,%2,%3};\n"
                        : "+f"(acc[2*p+1][0]), "+f"(acc[2*p+1][1]), "+f"(acc[2*p+1][2]), "+f"(acc[2*p+1][3])
                        : "r"(a[0]), "r"(a[1]), "r"(a[2]), "r"(a[3]), "r"(b2), "r"(b3));
                }
                {
                    uint32_t b0, b1;
                    uint32_t baddr = addrB0 + offB + 2u * (uint32_t)(ks * 16 * LDB + 32);
                    asm volatile(
                        "ldmatrix.sync.aligned.m8n8.x2.trans.shared.b16 {%0,%1}, [%2];\n"
                        : "=r"(b0), "=r"(b1) : "r"(baddr));
                    asm volatile(
                        "mma.sync.aligned.m16n8k16.row.col.f32.f16.f16.f32 "
                        "{%0,%1,%2,%3}, {%4,%5,%6,%7}, {%8,%9}, {%0,%1,%2,%3};\n"
                        : "+f"(acc[4][0]), "+f"(acc[4][1]), "+f"(acc[4][2]), "+f"(acc[4][3])
                        : "r"(a[0]), "r"(a[1]), "r"(a[2]), "r"(a[3]), "r"(b0), "r"(b1));
                }
            }

            if (pf || has_next)
                store_chunk((kc + 1) & 1);   // kc=3 stores next tile's chunk 0 into buf 0
            __syncthreads();
        }

        // ---- epilogue: stage band as cs2[j][row], j = col - row in [0,64] ----
        {
            const int row = m0 + (lane >> 2);
            #pragma unroll
            for (int t8 = 0; t8 < 5; t8++) {
                int colb = nst + t8 * 8 + 2 * (lane & 3);
                #pragma unroll
                for (int e = 0; e < 2; e++) {
                    int j0 = colb + e - row;
                    if (j0 >= 0 && j0 <= 64) cs2[j0 * LDJ + row] = acc[t8][e];
                    int j1 = colb + e - (row + 8);
                    if (j1 >= 0 && j1 <= 64) cs2[j1 * LDJ + row + 8] = acc[t8][2 + e];
                }
            }
        }
        __syncthreads();

        // ---- out[n, i, h, w0+wl] = cs2[64-i][wl] / 128 : lane-stride-1 LDS, 128B STG
        {
            const int bx = t & 3, h = (t >> 2) & (HH - 1), n = t >> 9;
            float* ob = out + (((size_t)n * NI) * HH + h) * WW + bx * WT;
            for (int idx = tid; idx < NI * WT; idx += 256) {
                int i  = idx >> 6;
                int wl = idx & 63;
                float v = cs2[(64 - i) * LDJ + wl] * (1.0f / 128.0f);
                ob[(size_t)i * HH * WW + wl] = v;
            }
        }
        // no extra sync needed: cs2 reads happen before each warp's next kc=0 sync,
        // and next cs2 writes only occur after the next tile's 4 chunk syncs.

        if (!has_next) break;
        t = tn;
        x1p = x1pN; x2p = x2pN; ok = okN;
    }
}

extern "C" void kernel_launch(void* const* d_in, const int* in_sizes, int n_in,
                              void* d_out, int out_size)
{
    const float* x1 = (const float*)d_in[0];
    const float* x2 = (const float*)d_in[1];
    float* out = (float*)d_out;
    (void)in_sizes; (void)n_in; (void)out_size;

    dim3 grid(GRIDX);
    dim3 block(256);
    corr_volume_kernel<<<grid, block>>>(x1, x2, out);
}